// round 4
// baseline (speedup 1.0000x reference)
#include <cuda_runtime.h>
#include <cstdint>
#include <cstddef>

// Problem constants
#define TT 8192
#define DD 1024
#define EE 64
#define CAPC 256
constexpr size_t TEC = (size_t)TT * EE * CAPC;   // 134217728 elements of combine

// Scratch (device globals; no allocation allowed)
__device__ float g_sum_gates[EE];
__device__ int   g_idx[TT];
__device__ float g_g15[TT];
__device__ int   g_loc[TT];

__global__ void init_kernel() {
    if (threadIdx.x < EE) g_sum_gates[threadIdx.x] = 0.0f;
}

// ---------------------------------------------------------------------------
// Kernel A: fused dim-reduce + cosine logits + softmax + argmax + gate sums.
// 256 threads = 8 warps, one warp per token. Grid = TT/8.
// ---------------------------------------------------------------------------
__global__ __launch_bounds__(256) void gate_kernel(
    const float* __restrict__ x,
    const float* __restrict__ Wred,
    const float* __restrict__ cent)
{
    __shared__ float4 Wsm[DD];    // W_red rows as float4 (D x 4)
    __shared__ float4 Csm[EE];    // normalized centroids
    __shared__ float  sg[EE];     // per-block gate sums

    const int tid  = threadIdx.x;
    const int warp = tid >> 5;
    const int lane = tid & 31;

    for (int i = tid; i < DD; i += 256)
        Wsm[i] = reinterpret_cast<const float4*>(Wred)[i];
    if (tid < EE) {
        float4 c = reinterpret_cast<const float4*>(cent)[tid];
        float n = sqrtf(c.x * c.x + c.y * c.y + c.z * c.z + c.w * c.w);
        float inv = 1.0f / fmaxf(n, 1e-4f);
        c.x *= inv; c.y *= inv; c.z *= inv; c.w *= inv;
        Csm[tid] = c;
        sg[tid]  = 0.0f;
    }
    __syncthreads();

    const int t = blockIdx.x * 8 + warp;
    const float* xr = x + (size_t)t * DD;

    // red[0..3] = x[t,:] @ W_red  (strided over lanes, butterfly-reduced)
    float a0 = 0.f, a1 = 0.f, a2 = 0.f, a3 = 0.f;
    #pragma unroll 4
    for (int i = lane; i < DD; i += 32) {
        float  xv = xr[i];
        float4 w  = Wsm[i];
        a0 = fmaf(xv, w.x, a0);
        a1 = fmaf(xv, w.y, a1);
        a2 = fmaf(xv, w.z, a2);
        a3 = fmaf(xv, w.w, a3);
    }
    #pragma unroll
    for (int o = 16; o > 0; o >>= 1) {
        a0 += __shfl_xor_sync(0xffffffffu, a0, o);
        a1 += __shfl_xor_sync(0xffffffffu, a1, o);
        a2 += __shfl_xor_sync(0xffffffffu, a2, o);
        a3 += __shfl_xor_sync(0xffffffffu, a3, o);
    }

    // Two logits per lane (experts lane, lane+32)
    float4 c0 = Csm[lane];
    float4 c1 = Csm[lane + 32];
    float l0 = a0 * c0.x + a1 * c0.y + a2 * c0.z + a3 * c0.w;
    float l1 = a0 * c1.x + a1 * c1.y + a2 * c1.z + a3 * c1.w;

    // softmax max
    float m = fmaxf(l0, l1);
    #pragma unroll
    for (int o = 16; o > 0; o >>= 1)
        m = fmaxf(m, __shfl_xor_sync(0xffffffffu, m, o));

    float e0 = __expf(l0 - m);
    float e1 = __expf(l1 - m);
    float s  = e0 + e1;
    #pragma unroll
    for (int o = 16; o > 0; o >>= 1)
        s += __shfl_xor_sync(0xffffffffu, s, o);
    const float invZ = 1.0f / s;

    // argmax over logits (first-occurrence tie-break, matching jnp.argmax)
    float bv = l0; int bi = lane;
    if (l1 > bv) { bv = l1; bi = lane + 32; }
    #pragma unroll
    for (int o = 16; o > 0; o >>= 1) {
        float ov = __shfl_xor_sync(0xffffffffu, bv, o);
        int   oi = __shfl_xor_sync(0xffffffffu, bi, o);
        if (ov > bv || (ov == bv && oi < bi)) { bv = ov; bi = oi; }
    }

    if (lane == 0) {
        g_idx[t] = bi;
        g_g15[t] = 1.5f * invZ;   // max logit => exp(0)/Z = 1/Z
    }

    // per-expert gate sums (for l_aux)
    atomicAdd(&sg[lane],      e0 * invZ);
    atomicAdd(&sg[lane + 32], e1 * invZ);
    __syncthreads();
    if (tid < EE) atomicAdd(&g_sum_gates[tid], sg[tid]);
}

// ---------------------------------------------------------------------------
// Kernel B: order-preserving per-expert positions (cumsum of mask1),
// expert_counts, and l_aux. Single block of 1024 threads, 8 chunks.
// ---------------------------------------------------------------------------
__global__ __launch_bounds__(1024) void scan_kernel(float* __restrict__ out)
{
    __shared__ int   hist[32][EE];
    __shared__ int   off[32][EE];
    __shared__ int   running[EE];
    __shared__ float red[EE];

    const int tid  = threadIdx.x;
    const int warp = tid >> 5;
    const int lane = tid & 31;

    if (tid < EE) running[tid] = 0;

    for (int c = 0; c < 8; c++) {
        reinterpret_cast<int*>(hist)[tid]        = 0;
        reinterpret_cast<int*>(hist)[tid + 1024] = 0;
        __syncthreads();

        const int t = c * 1024 + tid;
        const int e = g_idx[t];
        unsigned mask = __match_any_sync(0xffffffffu, e);
        int rank = __popc(mask & ((1u << lane) - 1u));
        if (rank == 0) hist[warp][e] = __popc(mask);
        __syncthreads();

        if (tid < EE) {
            int base = running[tid];
            #pragma unroll
            for (int w = 0; w < 32; w++) {
                off[w][tid] = base;
                base += hist[w][tid];
            }
            running[tid] = base;
        }
        __syncthreads();

        g_loc[t] = off[warp][e] + rank;
        __syncthreads();
    }

    // expert_counts (pre-capacity) + l_aux
    if (tid < EE) {
        int cnt = running[tid];
        out[1 + 2 * TEC + (size_t)tid] = (float)cnt;
        red[tid] = g_sum_gates[tid] * (float)cnt;
    }
    __syncthreads();
    if (tid == 0) {
        float ssum = 0.0f;
        #pragma unroll
        for (int e2 = 0; e2 < EE; e2++) ssum += red[e2];
        // l_aux = E * sum(me*ce) = E * sum(sg*cnt) / T^2
        out[0] = (float)EE * ssum / ((float)TT * (float)TT);
    }
}

// ---------------------------------------------------------------------------
// Kernel C: scatter the <= 8192 nonzeros into combine + dispatch_mask.
// ---------------------------------------------------------------------------
__global__ __launch_bounds__(256) void scatter_kernel(float* __restrict__ out)
{
    const int t = blockIdx.x * 256 + threadIdx.x;
    const int e = g_idx[t];
    const int p = g_loc[t];
    if (p < CAPC) {
        size_t o = 1 + ((size_t)t * EE + e) * (size_t)CAPC + (size_t)p;
        out[o]       = g_g15[t];   // combine value
        out[o + TEC] = 1.0f;       // dispatch_mask (cast to float)
    }
}

extern "C" void kernel_launch(void* const* d_in, const int* in_sizes, int n_in,
                              void* d_out, int out_size)
{
    const float* x    = (const float*)d_in[0];  // [T, D]
    const float* Wred = (const float*)d_in[1];  // [D, 4]
    const float* cent = (const float*)d_in[2];  // [E, 4]
    float* out = (float*)d_out;

    // Zero the whole output (combine/dispatch are ~all zeros; buffer is poisoned).
    cudaMemsetAsync(d_out, 0, (size_t)out_size * sizeof(float), 0);

    init_kernel<<<1, 64>>>();
    gate_kernel<<<TT / 8, 256>>>(x, Wred, cent);
    scan_kernel<<<1, 1024>>>(out);
    scatter_kernel<<<TT / 256, 256>>>(out);
}